// round 2
// baseline (speedup 1.0000x reference)
#include <cuda_runtime.h>
#include <math.h>
#include <stdint.h>

// ---------------- problem constants ----------------
#define Bv     64
#define Lv     256
#define Ev     1600
#define Pv     100
#define PSv    4
#define Nv     400          // P*PS
#define NPAD   512
#define Mv     16384        // B*L
#define Kv     1600

// output layout (floats)
//   [0 , 6400)                 prototype_distances [B,100]
//   [6400 , 556928)            dist0 [B,34,253]   (64*34*253 = 550528)
//   [556928 , 1084928)         dist1 [B,33,250]   (64*33*250 = 528000)
//   [1084928 , 1606592)        dist2 [B,33,247]   (64*33*247 = 521664)
//   [1606592 , 1606720)        class_out [B,2]
#define OFF_D0   6400
#define OFF_D1   556928
#define OFF_D2   1084928
#define OFF_FC   1606592

// ---------------- device scratch ----------------
static __device__ float g_Yt[(size_t)Nv * Mv];     // Y transposed [n][m]  (~26.2 MB)
static __device__ float g_Wt[(size_t)Kv * NPAD];   // W [k][n], zero-padded to NPAD
static __device__ float g_S[Mv];                   // per-row sum of squares
static __device__ float g_P2[Pv];                  // per-proto sum of squares

// ---------------- prep kernels ----------------
__global__ void zero_w_kernel() {
    int i = blockIdx.x * 256 + threadIdx.x;        // grid 3200*256 = 819200 = Kv*NPAD
    g_Wt[i] = 0.0f;
}

__global__ void prep_w_kernel(const float* __restrict__ proto) {
    int p = blockIdx.x;                             // 100 blocks
    __shared__ float red[256];
    float s = 0.0f;
    for (int i = threadIdx.x; i < Ev * PSv; i += 256) {
        int e = i >> 2, k = i & 3;
        float v = proto[(size_t)p * (Ev * PSv) + i];
        g_Wt[(size_t)e * NPAD + p * 4 + k] = v;
        s += v * v;
    }
    red[threadIdx.x] = s;
    __syncthreads();
    for (int st = 128; st > 0; st >>= 1) {
        if (threadIdx.x < st) red[threadIdx.x] += red[threadIdx.x + st];
        __syncthreads();
    }
    if (threadIdx.x == 0) g_P2[p] = red[0];
}

__global__ void sumsq_kernel(const float* __restrict__ X) {
    int row  = blockIdx.x * 8 + (threadIdx.x >> 5); // grid 2048 -> 16384 rows
    int lane = threadIdx.x & 31;
    const float* xr = X + (size_t)row * Ev;
    float s = 0.0f;
    for (int i = lane; i < Ev; i += 32) {
        float v = xr[i];
        s += v * v;
    }
    #pragma unroll
    for (int o = 16; o > 0; o >>= 1) s += __shfl_xor_sync(0xffffffffu, s, o);
    if (lane == 0) g_S[row] = s;
}

// ---------------- GEMM: Yt[n][m] = sum_k X[m][k] * Wt[k][n] ----------------
// BM=128, BN=128, BK=16, 256 threads, 8x8 per thread, packed f32x2 FMA.

#define PACK2(dst, s)  asm("mov.b64 %0, {%1, %1};" : "=l"(dst) : "f"(s))
#define FMA2(c, a, b)  asm("fma.rn.f32x2 %0, %1, %2, %0;" : "+l"(c) : "l"(a), "l"(b))

__device__ __forceinline__ float pick_half(unsigned long long u, int hi) {
    float2 f = *reinterpret_cast<float2*>(&u);
    return hi ? f.y : f.x;
}

__global__ void __launch_bounds__(256)
gemm_kernel(const float* __restrict__ X) {
    __shared__ __align__(16) float As[16 * 128];   // As[k][m]
    __shared__ __align__(16) float Bs[16 * 128];   // Bs[k][n]

    const int nb = blockIdx.x;          // 0..3   (n fastest -> L2 reuse of X stripe)
    const int mb = blockIdx.y;          // 0..127
    const int m0 = mb * 128;
    const int n0 = nb * 128;
    const int tid = threadIdx.x;
    const int tx = tid & 15;            // n direction
    const int ty = tid >> 4;            // m direction

    unsigned long long acc[8][4];
    #pragma unroll
    for (int i = 0; i < 8; ++i)
        #pragma unroll
        for (int j = 0; j < 4; ++j) acc[i][j] = 0ull;

    for (int kt = 0; kt < Kv; kt += 16) {
        // load A tile 128x16 (transpose into As[k][m])
        #pragma unroll
        for (int u = 0; u < 2; ++u) {
            int f  = tid + u * 256;
            int r  = f >> 2;            // m row 0..127
            int c4 = f & 3;             // which float4 in the 16-wide k strip
            float4 v = *reinterpret_cast<const float4*>(
                X + (size_t)(m0 + r) * Kv + kt + c4 * 4);
            As[(c4 * 4 + 0) * 128 + r] = v.x;
            As[(c4 * 4 + 1) * 128 + r] = v.y;
            As[(c4 * 4 + 2) * 128 + r] = v.z;
            As[(c4 * 4 + 3) * 128 + r] = v.w;
        }
        // load B tile 16x128
        #pragma unroll
        for (int u = 0; u < 2; ++u) {
            int f = tid + u * 256;
            int r = f >> 5;             // k row 0..15
            int c = f & 31;             // float4 col
            *reinterpret_cast<float4*>(Bs + r * 128 + c * 4) =
                *reinterpret_cast<const float4*>(
                    g_Wt + (size_t)(kt + r) * NPAD + n0 + c * 4);
        }
        __syncthreads();

        #pragma unroll
        for (int k = 0; k < 16; ++k) {
            float4 a0 = *reinterpret_cast<const float4*>(As + k * 128 + ty * 4);
            float4 a1 = *reinterpret_cast<const float4*>(As + k * 128 + 64 + ty * 4);
            unsigned long long am[8];
            PACK2(am[0], a0.x); PACK2(am[1], a0.y);
            PACK2(am[2], a0.z); PACK2(am[3], a0.w);
            PACK2(am[4], a1.x); PACK2(am[5], a1.y);
            PACK2(am[6], a1.z); PACK2(am[7], a1.w);

            const ulonglong2* brow = reinterpret_cast<const ulonglong2*>(Bs + k * 128);
            ulonglong2 bq0 = brow[tx];        // n = tx*4   .. tx*4+3
            ulonglong2 bq1 = brow[16 + tx];   // n = 64+tx*4 ..
            unsigned long long bp[4] = {bq0.x, bq0.y, bq1.x, bq1.y};

            #pragma unroll
            for (int i = 0; i < 8; ++i) {
                FMA2(acc[i][0], am[i], bp[0]);
                FMA2(acc[i][1], am[i], bp[1]);
                FMA2(acc[i][2], am[i], bp[2]);
                FMA2(acc[i][3], am[i], bp[3]);
            }
        }
        __syncthreads();
    }

    // epilogue: store transposed, guarded to n < 400
    #pragma unroll
    for (int jj = 0; jj < 8; ++jj) {
        int nl = (jj < 4) ? (tx * 4 + jj) : (64 + tx * 4 + (jj - 4));
        int n = n0 + nl;
        if (n < Nv) {
            int jp = (jj < 4) ? (jj >> 1) : (2 + ((jj - 4) >> 1));
            int hi = jj & 1;
            float4 v0, v1;
            v0.x = pick_half(acc[0][jp], hi);
            v0.y = pick_half(acc[1][jp], hi);
            v0.z = pick_half(acc[2][jp], hi);
            v0.w = pick_half(acc[3][jp], hi);
            v1.x = pick_half(acc[4][jp], hi);
            v1.y = pick_half(acc[5][jp], hi);
            v1.z = pick_half(acc[6][jp], hi);
            v1.w = pick_half(acc[7][jp], hi);
            *reinterpret_cast<float4*>(g_Yt + (size_t)n * Mv + m0 + ty * 4) = v0;
            *reinterpret_cast<float4*>(g_Yt + (size_t)n * Mv + m0 + 64 + ty * 4) = v1;
        }
    }
}

// ---------------- distances + per-(b,p) min ----------------
__global__ void dist_kernel(float* __restrict__ out) {
    int p = blockIdx.x % Pv;
    int b = blockIdx.x / Pv;
    int g = (p < 34) ? 0 : (p < 67) ? 1 : 2;
    int d = g + 1;
    int Lout = Lv - 3 * d;                      // 253 / 250 / 247
    int pbase = (g == 0) ? 0 : (g == 1) ? 34 : 67;
    int pl = p - pbase;
    int nf = (g == 0) ? 34 : 33;
    size_t dbase = (g == 0) ? OFF_D0 : (g == 1) ? OFF_D1 : OFF_D2;

    int l = threadIdx.x;
    float val = 3.402823466e38f;
    if (l < Lout) {
        int m = b * Lv + l;
        float xp = 0.0f, x2 = 0.0f;
        #pragma unroll
        for (int k = 0; k < PSv; ++k) {
            xp += g_Yt[(size_t)(p * 4 + k) * Mv + m + k * d];
            x2 += g_S[m + k * d];
        }
        val = sqrtf(fabsf(x2 - 2.0f * xp + g_P2[p]));
        out[dbase + ((size_t)b * nf + pl) * Lout + l] = val;
    }
    __shared__ float red[256];
    red[threadIdx.x] = val;
    __syncthreads();
    for (int st = 128; st > 0; st >>= 1) {
        if (threadIdx.x < st)
            red[threadIdx.x] = fminf(red[threadIdx.x], red[threadIdx.x + st]);
        __syncthreads();
    }
    if (threadIdx.x == 0) out[b * Pv + p] = red[0];
}

// ---------------- final fc ----------------
__global__ void fc_kernel(const float* __restrict__ fcw, float* __restrict__ out) {
    int b = blockIdx.x;
    __shared__ float s0[128], s1[128];
    int t = threadIdx.x;
    float v0 = 0.0f, v1 = 0.0f;
    if (t < Pv) {
        float pd = out[b * Pv + t];
        v0 = pd * fcw[t];
        v1 = pd * fcw[Pv + t];
    }
    s0[t] = v0; s1[t] = v1;
    __syncthreads();
    for (int st = 64; st > 0; st >>= 1) {
        if (t < st) { s0[t] += s0[t + st]; s1[t] += s1[t + st]; }
        __syncthreads();
    }
    if (t == 0) {
        out[OFF_FC + b * 2 + 0] = s0[0];
        out[OFF_FC + b * 2 + 1] = s1[0];
    }
}

// ---------------- launch ----------------
extern "C" void kernel_launch(void* const* d_in, const int* in_sizes, int n_in,
                              void* d_out, int out_size) {
    const float* emb   = (const float*)d_in[0];   // [64,256,1600]
    const float* proto = (const float*)d_in[1];   // [100,1600,4]
    const float* fcw   = (const float*)d_in[2];   // [2,100]
    float* out = (float*)d_out;

    zero_w_kernel<<<3200, 256>>>();
    prep_w_kernel<<<100, 256>>>(proto);
    sumsq_kernel<<<2048, 256>>>(emb);
    gemm_kernel<<<dim3(4, 128), 256>>>(emb);
    dist_kernel<<<Bv * Pv, 256>>>(out);
    fc_kernel<<<Bv, 128>>>(fcw, out);
}

// round 5
// speedup vs baseline: 4.4368x; 4.4368x over previous
#include <cuda_runtime.h>
#include <cuda_bf16.h>
#include <math.h>
#include <stdint.h>

// ---------------- problem constants ----------------
#define Bv     64
#define Lv     256
#define Ev     1600
#define Pv     100
#define Nv     400          // P*4
#define NPADv  448          // padded N (7 * 64)
#define Mv     16384        // B*L
#define Kv     1600
#define KC     32           // k per pipeline chunk
#define NCH    50           // Kv/KC

// output layout (floats)
#define OFF_D0   6400
#define OFF_D1   556928
#define OFF_D2   1084928
#define OFF_FC   1606592

// ---------------- device scratch ----------------
static __device__ float g_Yt[(size_t)Nv * Mv];   // Y^T [n][m]
static __device__ float g_S[Mv];                 // row sum of squares
static __device__ float g_P2[Pv];                // proto sum of squares
// B bf16 chunked: [kc][n(448)][32 k]  (64B per row-chunk)
static __device__ __align__(16) unsigned char g_Bc[(size_t)NCH * NPADv * 64];

// ---------------- smem layout (per CTA, dynamic) ----------------
//  buf s (s=0,1) at s*28160:
//    A tile: 128 rows * 80B   @ +0      (10240 B)
//    B tile: 224 rows * 80B   @ +10240  (17920 B)
#define BUFSTRIDE 28160
#define BOFF      10240
#define SMEM_DYN  (2 * BUFSTRIDE)

__device__ __forceinline__ uint32_t s2u(const void* p) {
    uint32_t a;
    asm("{ .reg .u64 t; cvta.to.shared.u64 t, %1; cvt.u32.u64 %0, t; }" : "=r"(a) : "l"(p));
    return a;
}

#define CP_ASYNC16(dst, src) \
    asm volatile("cp.async.cg.shared.global [%0], [%1], 16;" :: "r"(dst), "l"(src) : "memory")
#define CP_COMMIT() asm volatile("cp.async.commit_group;" ::: "memory")
#define CP_WAIT(n)  asm volatile("cp.async.wait_group %0;" :: "n"(n) : "memory")

#define LDM_X4(r0, r1, r2, r3, a) \
    asm volatile("ldmatrix.sync.aligned.m8n8.x4.shared.b16 {%0,%1,%2,%3}, [%4];" \
                 : "=r"(r0), "=r"(r1), "=r"(r2), "=r"(r3) : "r"(a))
#define LDM_X2(r0, r1, a) \
    asm volatile("ldmatrix.sync.aligned.m8n8.x2.shared.b16 {%0,%1}, [%2];" \
                 : "=r"(r0), "=r"(r1) : "r"(a))

#define MMA16816(d, a, b) \
    asm volatile("mma.sync.aligned.m16n8k16.row.col.f32.bf16.bf16.f32 " \
                 "{%0,%1,%2,%3}, {%4,%5,%6,%7}, {%8,%9}, {%0,%1,%2,%3};" \
                 : "+f"((d)[0]), "+f"((d)[1]), "+f"((d)[2]), "+f"((d)[3]) \
                 : "r"((a)[0]), "r"((a)[1]), "r"((a)[2]), "r"((a)[3]), \
                   "r"((b)[0]), "r"((b)[1]))

// ---------------- prep: zero + reorganize protolayer ----------------
__global__ void zero_bc_kernel() {
    size_t i = (size_t)blockIdx.x * 256 + threadIdx.x;     // grid 350*256 = 89600 uint4
    reinterpret_cast<uint4*>(g_Bc)[i] = make_uint4(0, 0, 0, 0);
}

__global__ void prep_b_kernel(const float* __restrict__ proto) {
    int p = blockIdx.x;                                     // 100 blocks
    __shared__ float red[256];
    float s = 0.0f;
    for (int i = threadIdx.x; i < Ev * 4; i += 256) {
        int e = i >> 2, t = i & 3;
        float v = proto[(size_t)p * (Ev * 4) + i];
        s += v * v;
        int n = 4 * p + t;
        int kc = e >> 5, dk = e & 31;
        *reinterpret_cast<__nv_bfloat16*>(
            g_Bc + ((size_t)kc * NPADv + n) * 64 + dk * 2) = __float2bfloat16(v);
    }
    red[threadIdx.x] = s;
    __syncthreads();
    for (int st = 128; st > 0; st >>= 1) {
        if (threadIdx.x < st) red[threadIdx.x] += red[threadIdx.x + st];
        __syncthreads();
    }
    if (threadIdx.x == 0) g_P2[p] = red[0];
}

// ---------------- A convert + STS helper ----------------
__device__ __forceinline__ void sts_a(char* dst, const float4 v[4], float& ssq) {
    #pragma unroll
    for (int g = 0; g < 2; ++g) {
        float4 a = v[2 * g], b = v[2 * g + 1];
        ssq += a.x * a.x + a.y * a.y + a.z * a.z + a.w * a.w
             + b.x * b.x + b.y * b.y + b.z * b.z + b.w * b.w;
        __nv_bfloat162 p0 = __floats2bfloat162_rn(a.x, a.y);
        __nv_bfloat162 p1 = __floats2bfloat162_rn(a.z, a.w);
        __nv_bfloat162 p2 = __floats2bfloat162_rn(b.x, b.y);
        __nv_bfloat162 p3 = __floats2bfloat162_rn(b.z, b.w);
        uint4 w;
        w.x = *reinterpret_cast<uint32_t*>(&p0);
        w.y = *reinterpret_cast<uint32_t*>(&p1);
        w.z = *reinterpret_cast<uint32_t*>(&p2);
        w.w = *reinterpret_cast<uint32_t*>(&p3);
        *reinterpret_cast<uint4*>(dst + g * 16) = w;
    }
}

// ---------------- HMMA GEMM: Yt[n][m] = sum_k X[m][k]*W[k][n] ----------------
__global__ void __launch_bounds__(256, 1)
gemm_mma_kernel(const float* __restrict__ X) {
    extern __shared__ __align__(128) char smem[];
    const uint32_t sb = s2u(smem);
    const int tid  = threadIdx.x;
    const int wid  = tid >> 5;
    const int lane = tid & 31;
    const int nb = blockIdx.x;              // 0..1
    const int m0 = blockIdx.y * 128;
    const int n0 = nb * 224;

    const int m_warp = (wid >> 2) * 64;     // 0 / 64
    const int n_warp = (wid & 3) * 56;      // 0,56,112,168

    // ---- per-lane ldmatrix base offsets (within a buffer) ----
    const uint32_t aA = sb + (uint32_t)(m_warp + (lane & 15)) * 80 + (lane >> 4) * 16;
    const uint32_t aB4 = sb + BOFF +
        (uint32_t)(n_warp + ((lane >> 4) << 3) + (lane & 7)) * 80 + ((lane >> 3) & 1) * 16;
    const int l15 = lane & 15;
    const uint32_t aB2 = sb + BOFF +
        (uint32_t)(n_warp + 48 + (l15 & 7)) * 80 + ((l15 >> 3) & 1) * 16;

    // ---- A global source: this thread's 16-float strip per chunk ----
    const int r = tid >> 1;                 // row 0..127
    const int h = tid & 1;                  // k half
    const float4* xs = reinterpret_cast<const float4*>(X + (size_t)(m0 + r) * Kv) + h * 4;
    char* aDst0 = smem + r * 80 + h * 32;   // + buf*BUFSTRIDE

    float acc[4][7][4];
    #pragma unroll
    for (int i = 0; i < 4; ++i)
        #pragma unroll
        for (int j = 0; j < 7; ++j)
            #pragma unroll
            for (int q = 0; q < 4; ++q) acc[i][j][q] = 0.0f;

    float ssq = 0.0f;
    float4 rA[4];

    // ---- prologue: chunk 0 -> buf0; prefetch chunk 1 ----
    {
        #pragma unroll
        for (int j = 0; j < 4; ++j) rA[j] = xs[j];
        sts_a(aDst0, rA, ssq);
        const char* bsrc = (const char*)(g_Bc + (size_t)n0 * 64);   // kc=0
        for (int i = tid; i < 896; i += 256)
            CP_ASYNC16(sb + BOFF + (i >> 2) * 80 + (i & 3) * 16,
                       bsrc + (i >> 2) * 64 + (i & 3) * 16);
        CP_COMMIT();
        // prefetch chunk 1
        #pragma unroll
        for (int j = 0; j < 4; ++j) rA[j] = xs[8 + j];
        const char* bsrc1 = (const char*)(g_Bc + ((size_t)NPADv + n0) * 64);
        for (int i = tid; i < 896; i += 256)
            CP_ASYNC16(sb + BUFSTRIDE + BOFF + (i >> 2) * 80 + (i & 3) * 16,
                       bsrc1 + (i >> 2) * 64 + (i & 3) * 16);
        CP_COMMIT();
        CP_WAIT(1);
        __syncthreads();
    }

    for (int kc = 0; kc < NCH; ++kc) {
        const uint32_t bo = (kc & 1) ? BUFSTRIDE : 0;
        // ---- compute chunk kc ----
        #pragma unroll
        for (int ks = 0; ks < 2; ++ks) {
            uint32_t afr[4][4];
            #pragma unroll
            for (int mf = 0; mf < 4; ++mf)
                LDM_X4(afr[mf][0], afr[mf][1], afr[mf][2], afr[mf][3],
                       aA + bo + mf * 1280 + ks * 32);
            uint32_t bfr[7][2];
            #pragma unroll
            for (int p = 0; p < 3; ++p)
                LDM_X4(bfr[2 * p][0], bfr[2 * p][1], bfr[2 * p + 1][0], bfr[2 * p + 1][1],
                       aB4 + bo + p * 1280 + ks * 32);
            LDM_X2(bfr[6][0], bfr[6][1], aB2 + bo + ks * 32);
            #pragma unroll
            for (int mf = 0; mf < 4; ++mf)
                #pragma unroll
                for (int nf = 0; nf < 7; ++nf)
                    MMA16816(acc[mf][nf], afr[mf], bfr[nf]);
        }
        // ---- stage chunk kc+1 / prefetch kc+2 ----
        if (kc < NCH - 1) {
            __syncthreads();
            const uint32_t bn = (kc & 1) ? 0 : BUFSTRIDE;   // next buffer
            sts_a(aDst0 + bn, rA, ssq);
            if (kc < NCH - 2) {
                #pragma unroll
                for (int j = 0; j < 4; ++j) rA[j] = xs[(kc + 2) * 8 + j];
                const char* bsrc = (const char*)(g_Bc + ((size_t)(kc + 2) * NPADv + n0) * 64);
                for (int i = tid; i < 896; i += 256)
                    CP_ASYNC16(sb + bo + BOFF + (i >> 2) * 80 + (i & 3) * 16,
                               bsrc + (i >> 2) * 64 + (i & 3) * 16);
                CP_COMMIT();
                CP_WAIT(1);
            } else {
                CP_WAIT(0);
            }
            __syncthreads();
        }
    }

    // ---- fused sumsq (nb==0 only; both blocks compute identical values) ----
    if (nb == 0) {
        float tot = ssq + __shfl_xor_sync(0xffffffffu, ssq, 1);
        if (h == 0) g_S[m0 + r] = tot;
    }

    // ---- epilogue: acc -> g_Yt[n][m], guard n < 400 ----
    #pragma unroll
    for (int mf = 0; mf < 4; ++mf) {
        const int mbase = m0 + m_warp + mf * 16 + (lane >> 2);
        #pragma unroll
        for (int nf = 0; nf < 7; ++nf) {
            const int nbase = n0 + n_warp + nf * 8 + 2 * (lane & 3);
            if (nbase < Nv) {
                g_Yt[(size_t)nbase * Mv + mbase]     = acc[mf][nf][0];
                g_Yt[(size_t)nbase * Mv + mbase + 8] = acc[mf][nf][2];
            }
            if (nbase + 1 < Nv) {
                g_Yt[(size_t)(nbase + 1) * Mv + mbase]     = acc[mf][nf][1];
                g_Yt[(size_t)(nbase + 1) * Mv + mbase + 8] = acc[mf][nf][3];
            }
        }
    }
}

// ---------------- distances + per-(b,p) min ----------------
__global__ void dist_kernel(float* __restrict__ out) {
    int p = blockIdx.x % Pv;
    int b = blockIdx.x / Pv;
    int g = (p < 34) ? 0 : (p < 67) ? 1 : 2;
    int d = g + 1;
    int Lout = Lv - 3 * d;
    int pbase = (g == 0) ? 0 : (g == 1) ? 34 : 67;
    int pl = p - pbase;
    int nf = (g == 0) ? 34 : 33;
    size_t dbase = (g == 0) ? OFF_D0 : (g == 1) ? OFF_D1 : OFF_D2;

    int l = threadIdx.x;
    float val = 3.402823466e38f;
    if (l < Lout) {
        int m = b * Lv + l;
        float xp = 0.0f, x2 = 0.0f;
        #pragma unroll
        for (int k = 0; k < 4; ++k) {
            xp += g_Yt[(size_t)(p * 4 + k) * Mv + m + k * d];
            x2 += g_S[m + k * d];
        }
        val = sqrtf(fabsf(x2 - 2.0f * xp + g_P2[p]));
        out[dbase + ((size_t)b * nf + pl) * Lout + l] = val;
    }
    __shared__ float red[256];
    red[threadIdx.x] = val;
    __syncthreads();
    for (int st = 128; st > 0; st >>= 1) {
        if (threadIdx.x < st)
            red[threadIdx.x] = fminf(red[threadIdx.x], red[threadIdx.x + st]);
        __syncthreads();
    }
    if (threadIdx.x == 0) out[b * Pv + p] = red[0];
}

// ---------------- final fc ----------------
__global__ void fc_kernel(const float* __restrict__ fcw, float* __restrict__ out) {
    int b = blockIdx.x;
    __shared__ float s0[128], s1[128];
    int t = threadIdx.x;
    float v0 = 0.0f, v1 = 0.0f;
    if (t < Pv) {
        float pd = out[b * Pv + t];
        v0 = pd * fcw[t];
        v1 = pd * fcw[Pv + t];
    }
    s0[t] = v0; s1[t] = v1;
    __syncthreads();
    for (int st = 64; st > 0; st >>= 1) {
        if (t < st) { s0[t] += s0[t + st]; s1[t] += s1[t + st]; }
        __syncthreads();
    }
    if (t == 0) {
        out[OFF_FC + b * 2 + 0] = s0[0];
        out[OFF_FC + b * 2 + 1] = s1[0];
    }
}

// ---------------- launch ----------------
extern "C" void kernel_launch(void* const* d_in, const int* in_sizes, int n_in,
                              void* d_out, int out_size) {
    const float* emb   = (const float*)d_in[0];   // [64,256,1600]
    const float* proto = (const float*)d_in[1];   // [100,1600,4]
    const float* fcw   = (const float*)d_in[2];   // [2,100]
    float* out = (float*)d_out;

    static int smem_set = 0;
    if (!smem_set) {
        cudaFuncSetAttribute(gemm_mma_kernel,
                             cudaFuncAttributeMaxDynamicSharedMemorySize, SMEM_DYN);
        smem_set = 1;
    }

    zero_bc_kernel<<<350, 256>>>();
    prep_b_kernel<<<100, 256>>>(proto);
    gemm_mma_kernel<<<dim3(2, 128), 256, SMEM_DYN>>>(emb);
    dist_kernel<<<Bv * Pv, 256>>>(out);
    fc_kernel<<<Bv, 128>>>(fcw, out);
}

// round 6
// speedup vs baseline: 4.4531x; 1.0037x over previous
#include <cuda_runtime.h>
#include <cuda_bf16.h>
#include <math.h>
#include <stdint.h>

// ---------------- problem constants ----------------
#define Bv     64
#define Lv     256
#define Ev     1600
#define Pv     100
#define Nv     400          // P*4
#define NPADv  448          // padded N
#define NTILE  112          // per-CTA n tile
#define Mv     16384        // B*L
#define Kv     1600
#define NCH    50           // Kv/32

// output layout (floats)
#define OFF_D0   6400
#define OFF_D1   556928
#define OFF_D2   1084928
#define OFF_FC   1606592

// ---------------- device scratch ----------------
static __device__ float g_Yt[(size_t)Nv * Mv];   // Y^T [n][m]
static __device__ float g_S[Mv];                 // row sum of squares
static __device__ float g_P2[Pv];                // proto sum of squares
// B bf16 chunked: [kc][n(448)][32 k]  (64B per row-chunk)
static __device__ __align__(16) unsigned char g_Bc[(size_t)NCH * NPADv * 64];

// ---------------- smem layout (per CTA, dynamic) ----------------
//  buf s (s=0,1) at s*19200:
//    A tile: 128 rows * 80B @ +0      (10240 B)
//    B tile: 112 rows * 80B @ +10240  ( 8960 B)
#define BUFSTRIDE 19200
#define BOFF      10240
#define SMEM_DYN  (2 * BUFSTRIDE)

__device__ __forceinline__ uint32_t s2u(const void* p) {
    uint32_t a;
    asm("{ .reg .u64 t; cvta.to.shared.u64 t, %1; cvt.u32.u64 %0, t; }" : "=r"(a) : "l"(p));
    return a;
}

#define CP_ASYNC16(dst, src) \
    asm volatile("cp.async.cg.shared.global [%0], [%1], 16;" :: "r"(dst), "l"(src) : "memory")
#define CP_COMMIT() asm volatile("cp.async.commit_group;" ::: "memory")
#define CP_WAIT(n)  asm volatile("cp.async.wait_group %0;" :: "n"(n) : "memory")

#define LDM_X4(r0, r1, r2, r3, a) \
    asm volatile("ldmatrix.sync.aligned.m8n8.x4.shared.b16 {%0,%1,%2,%3}, [%4];" \
                 : "=r"(r0), "=r"(r1), "=r"(r2), "=r"(r3) : "r"(a))
#define LDM_X2(r0, r1, a) \
    asm volatile("ldmatrix.sync.aligned.m8n8.x2.shared.b16 {%0,%1}, [%2];" \
                 : "=r"(r0), "=r"(r1) : "r"(a))

#define MMA16816(d, a, b) \
    asm volatile("mma.sync.aligned.m16n8k16.row.col.f32.bf16.bf16.f32 " \
                 "{%0,%1,%2,%3}, {%4,%5,%6,%7}, {%8,%9}, {%0,%1,%2,%3};" \
                 : "+f"((d)[0]), "+f"((d)[1]), "+f"((d)[2]), "+f"((d)[3]) \
                 : "r"((a)[0]), "r"((a)[1]), "r"((a)[2]), "r"((a)[3]), \
                   "r"((b)[0]), "r"((b)[1]))

// ---------------- prep: reorganize protolayer + zero padding ----------------
__global__ void prep_b_kernel(const float* __restrict__ proto) {
    int p = blockIdx.x;                                     // 0..111
    if (p >= Pv) {
        // zero 4 pad rows per block (n = 400..447)
        int n = Nv + (p - Pv) * 4 + (threadIdx.x & 3);
        int r4 = threadIdx.x >> 2;                          // 0..63
        uint4 z = make_uint4(0, 0, 0, 0);
        for (int j = r4; j < 200; j += 64) {                // 50 kc * 4 quads
            int kc = j >> 2, q = j & 3;
            *reinterpret_cast<uint4*>(g_Bc + ((size_t)kc * NPADv + n) * 64 + q * 16) = z;
        }
        return;
    }
    __shared__ float red[256];
    float s = 0.0f;
    for (int i = threadIdx.x; i < Ev * 4; i += 256) {
        int e = i >> 2, t = i & 3;
        float v = proto[(size_t)p * (Ev * 4) + i];
        s += v * v;
        int n = 4 * p + t;
        int kc = e >> 5, dk = e & 31;
        *reinterpret_cast<__nv_bfloat16*>(
            g_Bc + ((size_t)kc * NPADv + n) * 64 + dk * 2) = __float2bfloat16(v);
    }
    red[threadIdx.x] = s;
    __syncthreads();
    for (int st = 128; st > 0; st >>= 1) {
        if (threadIdx.x < st) red[threadIdx.x] += red[threadIdx.x + st];
        __syncthreads();
    }
    if (threadIdx.x == 0) g_P2[p] = red[0];
}

// ---------------- A convert + STS helper ----------------
__device__ __forceinline__ void sts_a(char* dst, const float4 v[4], float& ssq) {
    #pragma unroll
    for (int g = 0; g < 2; ++g) {
        float4 a = v[2 * g], b = v[2 * g + 1];
        ssq += a.x * a.x + a.y * a.y + a.z * a.z + a.w * a.w
             + b.x * b.x + b.y * b.y + b.z * b.z + b.w * b.w;
        __nv_bfloat162 p0 = __floats2bfloat162_rn(a.x, a.y);
        __nv_bfloat162 p1 = __floats2bfloat162_rn(a.z, a.w);
        __nv_bfloat162 p2 = __floats2bfloat162_rn(b.x, b.y);
        __nv_bfloat162 p3 = __floats2bfloat162_rn(b.z, b.w);
        uint4 w;
        w.x = *reinterpret_cast<uint32_t*>(&p0);
        w.y = *reinterpret_cast<uint32_t*>(&p1);
        w.z = *reinterpret_cast<uint32_t*>(&p2);
        w.w = *reinterpret_cast<uint32_t*>(&p3);
        *reinterpret_cast<uint4*>(dst + g * 16) = w;
    }
}

// ---------------- HMMA GEMM: Yt[n][m] = sum_k X[m][k]*W[k][n] ----------------
// grid (4, 128): 128x112 tile per CTA; 8 warps (4M x 2N), warp tile 32x56.
__global__ void __launch_bounds__(256, 2)
gemm_mma_kernel(const float* __restrict__ X) {
    extern __shared__ __align__(128) char smem[];
    const uint32_t sb = s2u(smem);
    const int tid  = threadIdx.x;
    const int wid  = tid >> 5;
    const int lane = tid & 31;
    const int nb = blockIdx.x;              // 0..3
    const int m0 = blockIdx.y * 128;
    const int n0 = nb * NTILE;

    const int m_warp = (wid >> 1) * 32;     // 0,32,64,96
    const int n_warp = (wid & 1) * 56;      // 0,56

    // ---- per-lane ldmatrix base offsets (within a buffer) ----
    const uint32_t aA = sb + (uint32_t)(m_warp + (lane & 15)) * 80 + (lane >> 4) * 16;
    const uint32_t aB4 = sb + BOFF +
        (uint32_t)(n_warp + ((lane >> 4) << 3) + (lane & 7)) * 80 + ((lane >> 3) & 1) * 16;
    const int l15 = lane & 15;
    const uint32_t aB2 = sb + BOFF +
        (uint32_t)(n_warp + 48 + (l15 & 7)) * 80 + ((l15 >> 3) & 1) * 16;

    // ---- A global source: this thread's 16-float strip per chunk ----
    const int r = tid >> 1;                 // row 0..127
    const int h = tid & 1;                  // k half
    const float4* xs = reinterpret_cast<const float4*>(X + (size_t)(m0 + r) * Kv) + h * 4;
    char* aDst0 = smem + r * 80 + h * 32;   // + buf*BUFSTRIDE

    float acc[2][7][4];
    #pragma unroll
    for (int i = 0; i < 2; ++i)
        #pragma unroll
        for (int j = 0; j < 7; ++j)
            #pragma unroll
            for (int q = 0; q < 4; ++q) acc[i][j][q] = 0.0f;

    float ssq = 0.0f;
    float4 rA[4];

    // ---- prologue: chunk 0 -> buf0; prefetch chunk 1 ----
    {
        #pragma unroll
        for (int j = 0; j < 4; ++j) rA[j] = xs[j];
        sts_a(aDst0, rA, ssq);
        const char* bsrc = (const char*)(g_Bc + (size_t)n0 * 64);   // kc=0
        for (int i = tid; i < 448; i += 256)
            CP_ASYNC16(sb + BOFF + (i >> 2) * 80 + (i & 3) * 16,
                       bsrc + (i >> 2) * 64 + (i & 3) * 16);
        CP_COMMIT();
        // prefetch chunk 1
        #pragma unroll
        for (int j = 0; j < 4; ++j) rA[j] = xs[8 + j];
        const char* bsrc1 = (const char*)(g_Bc + ((size_t)NPADv + n0) * 64);
        for (int i = tid; i < 448; i += 256)
            CP_ASYNC16(sb + BUFSTRIDE + BOFF + (i >> 2) * 80 + (i & 3) * 16,
                       bsrc1 + (i >> 2) * 64 + (i & 3) * 16);
        CP_COMMIT();
        CP_WAIT(1);
        __syncthreads();
    }

    for (int kc = 0; kc < NCH; ++kc) {
        const uint32_t bo = (kc & 1) ? BUFSTRIDE : 0;
        // ---- compute chunk kc ----
        #pragma unroll
        for (int ks = 0; ks < 2; ++ks) {
            uint32_t afr[2][4];
            #pragma unroll
            for (int mf = 0; mf < 2; ++mf)
                LDM_X4(afr[mf][0], afr[mf][1], afr[mf][2], afr[mf][3],
                       aA + bo + mf * 1280 + ks * 32);
            uint32_t bfr[7][2];
            #pragma unroll
            for (int p = 0; p < 3; ++p)
                LDM_X4(bfr[2 * p][0], bfr[2 * p][1], bfr[2 * p + 1][0], bfr[2 * p + 1][1],
                       aB4 + bo + p * 1280 + ks * 32);
            LDM_X2(bfr[6][0], bfr[6][1], aB2 + bo + ks * 32);
            #pragma unroll
            for (int mf = 0; mf < 2; ++mf)
                #pragma unroll
                for (int nf = 0; nf < 7; ++nf)
                    MMA16816(acc[mf][nf], afr[mf], bfr[nf]);
        }
        // ---- stage chunk kc+1 / prefetch kc+2 ----
        if (kc < NCH - 1) {
            __syncthreads();
            const uint32_t bn = (kc & 1) ? 0 : BUFSTRIDE;   // next buffer
            sts_a(aDst0 + bn, rA, ssq);
            if (kc < NCH - 2) {
                #pragma unroll
                for (int j = 0; j < 4; ++j) rA[j] = xs[(kc + 2) * 8 + j];
                const char* bsrc = (const char*)(g_Bc + ((size_t)(kc + 2) * NPADv + n0) * 64);
                for (int i = tid; i < 448; i += 256)
                    CP_ASYNC16(sb + bo + BOFF + (i >> 2) * 80 + (i & 3) * 16,
                               bsrc + (i >> 2) * 64 + (i & 3) * 16);
                CP_COMMIT();
                CP_WAIT(1);
            } else {
                CP_WAIT(0);
            }
            __syncthreads();
        }
    }

    // ---- fused sumsq (nb==0 only) ----
    if (nb == 0) {
        float tot = ssq + __shfl_xor_sync(0xffffffffu, ssq, 1);
        if (h == 0) g_S[m0 + r] = tot;
    }

    // ---- epilogue: acc -> g_Yt[n][m], guard n < 400 ----
    #pragma unroll
    for (int mf = 0; mf < 2; ++mf) {
        const int mbase = m0 + m_warp + mf * 16 + (lane >> 2);
        #pragma unroll
        for (int nf = 0; nf < 7; ++nf) {
            const int nbase = n0 + n_warp + nf * 8 + 2 * (lane & 3);
            if (nbase < Nv) {
                g_Yt[(size_t)nbase * Mv + mbase]     = acc[mf][nf][0];
                g_Yt[(size_t)nbase * Mv + mbase + 8] = acc[mf][nf][2];
            }
            if (nbase + 1 < Nv) {
                g_Yt[(size_t)(nbase + 1) * Mv + mbase]     = acc[mf][nf][1];
                g_Yt[(size_t)(nbase + 1) * Mv + mbase + 8] = acc[mf][nf][3];
            }
        }
    }
}

// ---------------- distances + per-(b,p) min: warp per (b,p) ----------------
__global__ void __launch_bounds__(256)
dist_kernel(float* __restrict__ out) {
    int idx  = blockIdx.x * 8 + (threadIdx.x >> 5);   // (b,p), grid 800 -> 6400
    int lane = threadIdx.x & 31;
    int p = idx % Pv;
    int b = idx / Pv;
    int g = (p < 34) ? 0 : (p < 67) ? 1 : 2;
    int d = g + 1;
    int Lout = Lv - 3 * d;                             // 253/250/247
    int pbase = (g == 0) ? 0 : (g == 1) ? 34 : 67;
    int nf = (g == 0) ? 34 : 33;
    size_t dbase = (g == 0) ? OFF_D0 : (g == 1) ? OFF_D1 : OFF_D2;
    float* orow = out + dbase + ((size_t)b * nf + (p - pbase)) * Lout;

    const float* y0 = g_Yt + (size_t)(p * 4) * Mv + b * Lv;
    const float* s0 = g_S + b * Lv;
    const float p2 = g_P2[p];

    float mn = 3.402823466e38f;
    #pragma unroll
    for (int it = 0; it < 8; ++it) {
        int l = lane + it * 32;
        if (l < Lout) {
            float xp = 0.0f, x2 = 0.0f;
            #pragma unroll
            for (int k = 0; k < 4; ++k) {
                xp += y0[(size_t)k * Mv + l + k * d];
                x2 += s0[l + k * d];
            }
            float val = sqrtf(fabsf(x2 - 2.0f * xp + p2));
            orow[l] = val;
            mn = fminf(mn, val);
        }
    }
    #pragma unroll
    for (int o = 16; o > 0; o >>= 1) mn = fminf(mn, __shfl_xor_sync(0xffffffffu, mn, o));
    if (lane == 0) out[b * Pv + p] = mn;
}

// ---------------- final fc ----------------
__global__ void fc_kernel(const float* __restrict__ fcw, float* __restrict__ out) {
    int b = blockIdx.x;
    __shared__ float s0[128], s1[128];
    int t = threadIdx.x;
    float v0 = 0.0f, v1 = 0.0f;
    if (t < Pv) {
        float pd = out[b * Pv + t];
        v0 = pd * fcw[t];
        v1 = pd * fcw[Pv + t];
    }
    s0[t] = v0; s1[t] = v1;
    __syncthreads();
    for (int st = 64; st > 0; st >>= 1) {
        if (t < st) { s0[t] += s0[t + st]; s1[t] += s1[t + st]; }
        __syncthreads();
    }
    if (t == 0) {
        out[OFF_FC + b * 2 + 0] = s0[0];
        out[OFF_FC + b * 2 + 1] = s1[0];
    }
}

// ---------------- launch ----------------
extern "C" void kernel_launch(void* const* d_in, const int* in_sizes, int n_in,
                              void* d_out, int out_size) {
    const float* emb   = (const float*)d_in[0];   // [64,256,1600]
    const float* proto = (const float*)d_in[1];   // [100,1600,4]
    const float* fcw   = (const float*)d_in[2];   // [2,100]
    float* out = (float*)d_out;

    static int smem_set = 0;
    if (!smem_set) {
        cudaFuncSetAttribute(gemm_mma_kernel,
                             cudaFuncAttributeMaxDynamicSharedMemorySize, SMEM_DYN);
        smem_set = 1;
    }

    prep_b_kernel<<<112, 256>>>(proto);
    gemm_mma_kernel<<<dim3(4, 128), 256, SMEM_DYN>>>(emb);
    dist_kernel<<<800, 256>>>(out);
    fc_kernel<<<Bv, 128>>>(fcw, out);
}